// round 8
// baseline (speedup 1.0000x reference)
#include <cuda_runtime.h>
#include <cuda_fp16.h>
#include <cstdint>
#include <math.h>

#define H_DIM 4096
#define E_DIM 64
#define TILE_M 128
#define KCHUNK 64
#define NCHUNKS (H_DIM / KCHUNK)   // 64
#define GAP_THRESH 2e-3f
#define CPAD 68

// stage layout (bytes): fp16 tiles, 128 B rows, SW128 swizzle
#define OFF_A 0                    // 128 x 64 fp16 = 16384 B
#define OFF_B 16384                // 64 x 64 fp16  =  8192 B
#define STAGE_BYTES 24576
#define SMEM_BYTES 49152           // 2 stages; epilogue C-stage overlays

// byte offset of (row, 16B-chunk c) in a SW128 128B-row tile
#define SWZ(r, c) ((uint32_t)((r) * 128 + (((c) ^ ((r) & 7)) << 4)))

__device__ __forceinline__ uint32_t smem_to_u32(const void* p) {
    uint32_t a;
    asm("{ .reg .u64 t; cvta.to.shared.u64 t, %1; cvt.u32.u64 %0, t; }" : "=r"(a) : "l"(p));
    return a;
}

#define LDSM_X4(r0, r1, r2, r3, addr)                                          \
    asm volatile("ldmatrix.sync.aligned.m8n8.x4.shared.b16 {%0,%1,%2,%3}, [%4];" \
                 : "=r"(r0), "=r"(r1), "=r"(r2), "=r"(r3) : "r"(addr))

__device__ __forceinline__ void mma_fp16(float* c, const uint32_t* a,
                                         uint32_t b0, uint32_t b1) {
    asm volatile(
        "mma.sync.aligned.m16n8k16.row.col.f32.f16.f16.f32 "
        "{%0,%1,%2,%3}, {%4,%5,%6,%7}, {%8,%9}, {%0,%1,%2,%3};"
        : "+f"(c[0]), "+f"(c[1]), "+f"(c[2]), "+f"(c[3])
        : "r"(a[0]), "r"(a[1]), "r"(a[2]), "r"(a[3]), "r"(b0), "r"(b1));
}

__device__ __forceinline__ uint32_t h2(float a, float b) {
    __half2 t = __floats2half2_rn(a, b);
    return *(uint32_t*)&t;
}

// ---------------------------------------------------------------------------
// Globals: W as fp16 + near-tie flag list
// ---------------------------------------------------------------------------
__device__ __half g_Wh[E_DIM * H_DIM];
__device__ int g_flag_count;
__device__ int g_flag_tokens[32768];

__global__ __launch_bounds__(256) void w_half(const float* __restrict__ W) {
    if (blockIdx.x == 0 && threadIdx.x == 0) g_flag_count = 0;
    for (int i = blockIdx.x * 256 + threadIdx.x; i < E_DIM * H_DIM; i += 256 * 256)
        g_Wh[i] = __float2half_rn(W[i]);
}

// ---------------------------------------------------------------------------
// Single-pass fp16 HMMA GEMM, double-buffered + fused epilogue.
// CTA: 128 tokens x 64 experts; warp w owns token rows 16w..16w+15.
// ---------------------------------------------------------------------------
__global__ __launch_bounds__(256, 2) void router_gemm_mma(const float* __restrict__ A,
                                                          float* __restrict__ C,
                                                          float* __restrict__ P,
                                                          float* __restrict__ IDX) {
    __shared__ __align__(16) char smem[SMEM_BYTES];
    const uint32_t sb = smem_to_u32(smem);
    float* Cs = (float*)smem;

    const int tid = threadIdx.x;
    const int wid = tid >> 5;
    const int lane = tid & 31;
    const long tokenBase = (long)blockIdx.x * TILE_M;

    float acc[8][4];
#pragma unroll
    for (int j = 0; j < 8; j++)
#pragma unroll
        for (int i = 0; i < 4; i++) acc[j][i] = 0.0f;

    // A loader: 2 threads/row; thread covers 32 k-elems (8 float4 -> 4 x 16B)
    const int arow = tid >> 1;           // 0..127
    const int ahalf = tid & 1;
    const float* aP = A + (tokenBase + arow) * H_DIM + ahalf * 32;
    // B loader: 4 threads/expert-row; 16 fp16 each (2 x 16B)
    const int bexp = tid & 63;
    const int bseg = tid >> 6;           // 0..3
    const __half* wP = g_Wh + (long)bexp * H_DIM + bseg * 16;

    // ldmatrix lane addressing
    const int lrowA = wid * 16 + (lane & 15);
    const uint32_t ahalfL = (uint32_t)((lane >> 4) & 1);
    const int ebase = (lane & 7) + ((lane >> 4) & 1) * 8;
    const uint32_t bhalfL = (uint32_t)((lane >> 3) & 1);

    // ---- prologue: chunk 0 ----
    float4 pa[8];
    uint4 wv0, wv1;
#pragma unroll
    for (int i = 0; i < 8; i++) pa[i] = *(const float4*)(aP + i * 4);
    wv0 = *(const uint4*)(wP);
    wv1 = *(const uint4*)(wP + 8);
    {
#pragma unroll
        for (int i = 0; i < 4; i++) {
            uint4 hc;
            hc.x = h2(pa[2 * i].x, pa[2 * i].y);
            hc.y = h2(pa[2 * i].z, pa[2 * i].w);
            hc.z = h2(pa[2 * i + 1].x, pa[2 * i + 1].y);
            hc.w = h2(pa[2 * i + 1].z, pa[2 * i + 1].w);
            *(uint4*)(smem + OFF_A + SWZ(arow, ahalf * 4 + i)) = hc;
        }
        *(uint4*)(smem + OFF_B + SWZ(bexp, bseg * 2)) = wv0;
        *(uint4*)(smem + OFF_B + SWZ(bexp, bseg * 2 + 1)) = wv1;
    }
    __syncthreads();

    for (int chunk = 0; chunk < NCHUNKS; chunk++) {
        const uint32_t cb = (uint32_t)((chunk & 1) * STAGE_BYTES);
        const uint32_t nb = (uint32_t)(((chunk + 1) & 1) * STAGE_BYTES);
        const bool more = (chunk + 1 < NCHUNKS);

        // prefetch next chunk into registers (overlaps MMA)
        if (more) {
            const int kb = (chunk + 1) * KCHUNK;
#pragma unroll
            for (int i = 0; i < 8; i++) pa[i] = *(const float4*)(aP + kb + i * 4);
            wv0 = *(const uint4*)(wP + kb);
            wv1 = *(const uint4*)(wP + kb + 8);
        }

        // compute: 4 k16-steps x 8 MMA
#pragma unroll
        for (int s = 0; s < 4; s++) {
            uint32_t av[4];
            {
                const uint32_t ch = (uint32_t)(2 * s) + ahalfL;
                const uint32_t ao = (uint32_t)(lrowA * 128) +
                                    ((ch ^ ((uint32_t)lrowA & 7)) << 4);
                LDSM_X4(av[0], av[1], av[2], av[3], sb + cb + OFF_A + ao);
            }
            uint32_t bv[16];
#pragma unroll
            for (int jt = 0; jt < 4; jt++) {
                const int erow = jt * 16 + ebase;
                const uint32_t ch = (uint32_t)(2 * s) + bhalfL;
                const uint32_t bo = (uint32_t)(erow * 128) +
                                    ((ch ^ ((uint32_t)erow & 7)) << 4);
                LDSM_X4(bv[4 * jt], bv[4 * jt + 1], bv[4 * jt + 2], bv[4 * jt + 3],
                        sb + cb + OFF_B + bo);
            }
#pragma unroll
            for (int jt = 0; jt < 4; jt++) {
                mma_fp16(acc[2 * jt], av, bv[4 * jt], bv[4 * jt + 1]);
                mma_fp16(acc[2 * jt + 1], av, bv[4 * jt + 2], bv[4 * jt + 3]);
            }
        }

        // convert + store next chunk into alternate buffer
        if (more) {
#pragma unroll
            for (int i = 0; i < 4; i++) {
                uint4 hc;
                hc.x = h2(pa[2 * i].x, pa[2 * i].y);
                hc.y = h2(pa[2 * i].z, pa[2 * i].w);
                hc.z = h2(pa[2 * i + 1].x, pa[2 * i + 1].y);
                hc.w = h2(pa[2 * i + 1].z, pa[2 * i + 1].w);
                *(uint4*)(smem + nb + OFF_A + SWZ(arow, ahalf * 4 + i)) = hc;
            }
            *(uint4*)(smem + nb + OFF_B + SWZ(bexp, bseg * 2)) = wv0;
            *(uint4*)(smem + nb + OFF_B + SWZ(bexp, bseg * 2 + 1)) = wv1;
        }
        __syncthreads();
    }

    // ---- stage logits to smem [128][CPAD] (overlays stage buffers) ----
    {
        const int r0 = wid * 16 + (lane >> 2);
        const int cbo = 2 * (lane & 3);
#pragma unroll
        for (int j = 0; j < 8; j++) {
            const int col = j * 8 + cbo;
            *(float2*)(Cs + r0 * CPAD + col) = make_float2(acc[j][0], acc[j][1]);
            *(float2*)(Cs + (r0 + 8) * CPAD + col) = make_float2(acc[j][2], acc[j][3]);
        }
    }
    __syncthreads();

    // ---- fused softmax + top-2 + flagging: warp w handles 16 tokens ----
#pragma unroll 1
    for (int t16 = 0; t16 < 16; t16++) {
        const int tok = wid * 16 + t16;
        const float v0 = Cs[tok * CPAD + lane];
        const float v1 = Cs[tok * CPAD + lane + 32];
        const long gtok = tokenBase + tok;

        float* crow = C + gtok * E_DIM;
        crow[lane] = v0;
        crow[lane + 32] = v1;

        float m = fmaxf(v0, v1);
#pragma unroll
        for (int o = 16; o; o >>= 1) m = fmaxf(m, __shfl_xor_sync(0xffffffffu, m, o));

        float e0 = __expf(v0 - m);
        float e1 = __expf(v1 - m);
        float s = e0 + e1;
#pragma unroll
        for (int o = 16; o; o >>= 1) s += __shfl_xor_sync(0xffffffffu, s, o);
        float inv = 1.0f / s;

        float* prow = P + gtok * E_DIM;
        prow[lane] = e0 * inv;
        prow[lane + 32] = e1 * inv;

        float bv; int bi;
        if (v0 >= v1) { bv = v0; bi = lane; } else { bv = v1; bi = lane + 32; }
#pragma unroll
        for (int o = 16; o; o >>= 1) {
            float ov = __shfl_xor_sync(0xffffffffu, bv, o);
            int   oi = __shfl_xor_sync(0xffffffffu, bi, o);
            if (ov > bv || (ov == bv && oi < bi)) { bv = ov; bi = oi; }
        }
        float c0 = (lane == bi) ? -INFINITY : v0;
        float c1 = (lane + 32 == bi) ? -INFINITY : v1;
        float sv; int si;
        if (c0 >= c1) { sv = c0; si = lane; } else { sv = c1; si = lane + 32; }
#pragma unroll
        for (int o = 16; o; o >>= 1) {
            float ov = __shfl_xor_sync(0xffffffffu, sv, o);
            int   oi = __shfl_xor_sync(0xffffffffu, si, o);
            if (ov > sv || (ov == sv && oi < si)) { sv = ov; si = oi; }
        }
        float d0 = (lane == bi || lane == si) ? -INFINITY : v0;
        float d1 = (lane + 32 == bi || lane + 32 == si) ? -INFINITY : v1;
        float tv = fmaxf(d0, d1);
#pragma unroll
        for (int o = 16; o; o >>= 1) tv = fmaxf(tv, __shfl_xor_sync(0xffffffffu, tv, o));

        if (lane == 0) {
            IDX[gtok * 2 + 0] = (float)bi;
            IDX[gtok * 2 + 1] = (float)si;
            if ((bv - sv) < GAP_THRESH || (sv - tv) < GAP_THRESH) {
                int slot = atomicAdd(&g_flag_count, 1);
                if (slot < 32768) g_flag_tokens[slot] = (int)gtok;
            }
        }
    }
}

// ---------------------------------------------------------------------------
// Exact fp64 recomputation for flagged near-tie tokens.
// ---------------------------------------------------------------------------
__global__ __launch_bounds__(64) void refine_ties(const float* __restrict__ A,
                                                  const float* __restrict__ W,
                                                  float* __restrict__ IDX) {
    __shared__ float sA[H_DIM];
    __shared__ double dred[2];
    __shared__ double dred2[2];
    __shared__ float af_s[E_DIM];

    int n = g_flag_count;
    if (n > 32768) n = 32768;

    const int e = threadIdx.x;
    const int lane = e & 31;
    const int wrp = e >> 5;

    for (int it = blockIdx.x; it < n; it += gridDim.x) {
        const int tok = g_flag_tokens[it];
        const float* arow = A + (long)tok * H_DIM;
        for (int k = threadIdx.x * 4; k < H_DIM; k += 64 * 4)
            *(float4*)(sA + k) = *(const float4*)(arow + k);
        __syncthreads();

        const float* wrow = W + (long)e * H_DIM;
        double a0 = 0, a1 = 0, a2 = 0, a3 = 0, a4 = 0, a5 = 0, a6 = 0, a7 = 0;
#pragma unroll 4
        for (int k = 0; k < H_DIM; k += 8) {
            float4 w0 = *(const float4*)(wrow + k);
            float4 w1 = *(const float4*)(wrow + k + 4);
            a0 = fma((double)sA[k + 0], (double)w0.x, a0);
            a1 = fma((double)sA[k + 1], (double)w0.y, a1);
            a2 = fma((double)sA[k + 2], (double)w0.z, a2);
            a3 = fma((double)sA[k + 3], (double)w0.w, a3);
            a4 = fma((double)sA[k + 4], (double)w1.x, a4);
            a5 = fma((double)sA[k + 5], (double)w1.y, a5);
            a6 = fma((double)sA[k + 6], (double)w1.z, a6);
            a7 = fma((double)sA[k + 7], (double)w1.w, a7);
        }
        double l = ((a0 + a1) + (a2 + a3)) + ((a4 + a5) + (a6 + a7));

        double mv = l;
#pragma unroll
        for (int o = 16; o; o >>= 1) {
            double ov = __shfl_xor_sync(0xffffffffu, mv, o);
            mv = ov > mv ? ov : mv;
        }
        if (lane == 0) dred[wrp] = mv;
        __syncthreads();
        const double m = dred[0] > dred[1] ? dred[0] : dred[1];

        const double ex = exp(l - m);
        double sm = ex;
#pragma unroll
        for (int o = 16; o; o >>= 1) sm += __shfl_xor_sync(0xffffffffu, sm, o);
        if (lane == 0) dred2[wrp] = sm;
        __syncthreads();
        const double s = dred2[0] + dred2[1];

        af_s[e] = (float)(ex / s);
        __syncthreads();

        if (e == 0) {
            int bi = 0;
#pragma unroll
            for (int i = 1; i < E_DIM; i++)
                if (af_s[i] > af_s[bi]) bi = i;
            int si = (bi == 0) ? 1 : 0;
#pragma unroll
            for (int i = 0; i < E_DIM; i++) {
                if (i == bi || i == si) continue;
                if (af_s[i] > af_s[si]) si = i;
            }
            IDX[(long)tok * 2 + 0] = (float)bi;
            IDX[(long)tok * 2 + 1] = (float)si;
        }
        __syncthreads();
    }
}

// ---------------------------------------------------------------------------
// d_out: [logits T*64 | affinities T*64 | indices-as-float T*2], fp32.
// ---------------------------------------------------------------------------
extern "C" void kernel_launch(void* const* d_in, const int* in_sizes, int n_in,
                              void* d_out, int out_size) {
    const float* A = (const float*)d_in[0];
    const float* W = (const float*)d_in[1];
    const int T = in_sizes[0] / H_DIM;  // 32768

    float* out = (float*)d_out;
    float* logits = out;
    float* affin  = out + (long)T * E_DIM;
    float* idx    = out + 2L * T * E_DIM;

    w_half<<<256, 256>>>(W);
    router_gemm_mma<<<T / TILE_M, 256>>>(A, logits, affin, idx);
    refine_ties<<<128, 64>>>(A, W, idx);
}

// round 9
// speedup vs baseline: 1.0471x; 1.0471x over previous
#include <cuda_runtime.h>
#include <cuda_fp16.h>
#include <cstdint>
#include <math.h>

#define H_DIM 4096
#define E_DIM 64
#define TILE_M 128
#define KCHUNK 32
#define NCHUNKS (H_DIM / KCHUNK)   // 128
#define GAP_THRESH 2e-3f
#define CPAD 68

// stage layout (bytes): fp16 tiles, 64 B rows, SW64 swizzle
#define OFF_A 0                    // 128 x 32 fp16 = 8192 B
#define OFF_B 8192                 // 64 x 32 fp16  = 4096 B
#define STAGE_BYTES 12288
#define SMEM_BYTES 34816           // 2 stages (24576) OR epilogue C-stage (34816)

// byte offset of (row, 16B-chunk c) in a SW64-swizzled 64B-row tile (c: 0..3)
#define SWZ(r, c) ((uint32_t)((r) * 64 + ((((c) ^ (((r) >> 1) & 3))) << 4)))

__device__ __forceinline__ uint32_t smem_to_u32(const void* p) {
    uint32_t a;
    asm("{ .reg .u64 t; cvta.to.shared.u64 t, %1; cvt.u32.u64 %0, t; }" : "=r"(a) : "l"(p));
    return a;
}

#define LDSM_X4(r0, r1, r2, r3, addr)                                          \
    asm volatile("ldmatrix.sync.aligned.m8n8.x4.shared.b16 {%0,%1,%2,%3}, [%4];" \
                 : "=r"(r0), "=r"(r1), "=r"(r2), "=r"(r3) : "r"(addr))

__device__ __forceinline__ void mma_fp16(float* c, const uint32_t* a,
                                         uint32_t b0, uint32_t b1) {
    asm volatile(
        "mma.sync.aligned.m16n8k16.row.col.f32.f16.f16.f32 "
        "{%0,%1,%2,%3}, {%4,%5,%6,%7}, {%8,%9}, {%0,%1,%2,%3};"
        : "+f"(c[0]), "+f"(c[1]), "+f"(c[2]), "+f"(c[3])
        : "r"(a[0]), "r"(a[1]), "r"(a[2]), "r"(a[3]), "r"(b0), "r"(b1));
}

__device__ __forceinline__ uint32_t h2(float a, float b) {
    __half2 t = __floats2half2_rn(a, b);
    return *(uint32_t*)&t;
}

// ---------------------------------------------------------------------------
// Globals: W as fp16 + near-tie flag list
// ---------------------------------------------------------------------------
__device__ __half g_Wh[E_DIM * H_DIM];
__device__ int g_flag_count;
__device__ int g_flag_tokens[32768];

__global__ __launch_bounds__(256) void w_half(const float* __restrict__ W) {
    if (blockIdx.x == 0 && threadIdx.x == 0) g_flag_count = 0;
    for (int i = blockIdx.x * 256 + threadIdx.x; i < E_DIM * H_DIM; i += 256 * 256)
        g_Wh[i] = __float2half_rn(W[i]);
}

// ---------------------------------------------------------------------------
// Single-pass fp16 HMMA GEMM, double-buffered, KCHUNK=32 (no-spill footprint).
// CTA: 128 tokens x 64 experts; warp w owns token rows 16w..16w+15.
// ---------------------------------------------------------------------------
__global__ __launch_bounds__(256, 2) void router_gemm_mma(const float* __restrict__ A,
                                                          float* __restrict__ C,
                                                          float* __restrict__ P,
                                                          float* __restrict__ IDX) {
    __shared__ __align__(16) char smem[SMEM_BYTES];
    const uint32_t sb = smem_to_u32(smem);
    float* Cs = (float*)smem;

    const int tid = threadIdx.x;
    const int wid = tid >> 5;
    const int lane = tid & 31;
    const long tokenBase = (long)blockIdx.x * TILE_M;

    float acc[8][4];
#pragma unroll
    for (int j = 0; j < 8; j++)
#pragma unroll
        for (int i = 0; i < 4; i++) acc[j][i] = 0.0f;

    // A loader: thread t -> row t>>1, 16 k-elems at (t&1)*16 (4 float4 regs)
    const int arow = tid >> 1;
    const int ahalf = tid & 1;
    const float* aP = A + (tokenBase + arow) * H_DIM + ahalf * 16;
    // B loader: thread t -> expert row t>>2, 16B chunk t&3 (8 fp16)
    const int bexp = tid >> 2;
    const int bch = tid & 3;
    const __half* wP = g_Wh + (long)bexp * H_DIM + bch * 8;

    // ldmatrix lane addressing (64B rows, SW64)
    const int lrowA = wid * 16 + (lane & 15);
    const uint32_t axr = (uint32_t)((lrowA >> 1) & 3);
    const uint32_t ahalfL = (uint32_t)((lane >> 4) & 1);
    const int ebase = (lane & 7) + ((lane >> 4) & 1) * 8;
    const uint32_t bhalfL = (uint32_t)((lane >> 3) & 1);

    // ---- prologue: chunk 0 ----
    float4 pa[4];
    uint4 wv;
#pragma unroll
    for (int i = 0; i < 4; i++) pa[i] = *(const float4*)(aP + i * 4);
    wv = *(const uint4*)(wP);
    {
        uint4 h0, h1;
        h0.x = h2(pa[0].x, pa[0].y); h0.y = h2(pa[0].z, pa[0].w);
        h0.z = h2(pa[1].x, pa[1].y); h0.w = h2(pa[1].z, pa[1].w);
        h1.x = h2(pa[2].x, pa[2].y); h1.y = h2(pa[2].z, pa[2].w);
        h1.z = h2(pa[3].x, pa[3].y); h1.w = h2(pa[3].z, pa[3].w);
        *(uint4*)(smem + OFF_A + SWZ(arow, ahalf * 2)) = h0;
        *(uint4*)(smem + OFF_A + SWZ(arow, ahalf * 2 + 1)) = h1;
        *(uint4*)(smem + OFF_B + SWZ(bexp, bch)) = wv;
    }
    __syncthreads();

    for (int chunk = 0; chunk < NCHUNKS; chunk++) {
        const uint32_t cb = (uint32_t)((chunk & 1) * STAGE_BYTES);
        const uint32_t nb = (uint32_t)(((chunk + 1) & 1) * STAGE_BYTES);
        const bool more = (chunk + 1 < NCHUNKS);

        // prefetch next chunk into registers (overlaps MMA)
        if (more) {
            const int kb = (chunk + 1) * KCHUNK;
#pragma unroll
            for (int i = 0; i < 4; i++) pa[i] = *(const float4*)(aP + kb + i * 4);
            wv = *(const uint4*)(wP + kb);
        }

        // compute: 2 k16-steps x 8 MMA
#pragma unroll
        for (int s = 0; s < 2; s++) {
            uint32_t av[4];
            {
                const uint32_t ch = (uint32_t)(2 * s) + ahalfL;
                const uint32_t ao = (uint32_t)(lrowA * 64) + ((ch ^ axr) << 4);
                LDSM_X4(av[0], av[1], av[2], av[3], sb + cb + OFF_A + ao);
            }
            uint32_t bv[16];
#pragma unroll
            for (int jt = 0; jt < 4; jt++) {
                const int erow = jt * 16 + ebase;
                const uint32_t ch = (uint32_t)(2 * s) + bhalfL;
                const uint32_t bo = (uint32_t)(erow * 64) +
                                    ((ch ^ (uint32_t)((erow >> 1) & 3)) << 4);
                LDSM_X4(bv[4 * jt], bv[4 * jt + 1], bv[4 * jt + 2], bv[4 * jt + 3],
                        sb + cb + OFF_B + bo);
            }
#pragma unroll
            for (int jt = 0; jt < 4; jt++) {
                mma_fp16(acc[2 * jt], av, bv[4 * jt], bv[4 * jt + 1]);
                mma_fp16(acc[2 * jt + 1], av, bv[4 * jt + 2], bv[4 * jt + 3]);
            }
        }

        // convert + store next chunk into alternate buffer
        if (more) {
            uint4 h0, h1;
            h0.x = h2(pa[0].x, pa[0].y); h0.y = h2(pa[0].z, pa[0].w);
            h0.z = h2(pa[1].x, pa[1].y); h0.w = h2(pa[1].z, pa[1].w);
            h1.x = h2(pa[2].x, pa[2].y); h1.y = h2(pa[2].z, pa[2].w);
            h1.z = h2(pa[3].x, pa[3].y); h1.w = h2(pa[3].z, pa[3].w);
            *(uint4*)(smem + nb + OFF_A + SWZ(arow, ahalf * 2)) = h0;
            *(uint4*)(smem + nb + OFF_A + SWZ(arow, ahalf * 2 + 1)) = h1;
            *(uint4*)(smem + nb + OFF_B + SWZ(bexp, bch)) = wv;
        }
        __syncthreads();
    }

    // ---- stage logits to smem [128][CPAD] (overlays stage buffers) ----
    {
        const int r0 = wid * 16 + (lane >> 2);
        const int cbo = 2 * (lane & 3);
#pragma unroll
        for (int j = 0; j < 8; j++) {
            const int col = j * 8 + cbo;
            *(float2*)(Cs + r0 * CPAD + col) = make_float2(acc[j][0], acc[j][1]);
            *(float2*)(Cs + (r0 + 8) * CPAD + col) = make_float2(acc[j][2], acc[j][3]);
        }
    }
    __syncthreads();

    // ---- fused softmax + top-2 + flagging: warp w handles 16 tokens ----
#pragma unroll 1
    for (int t16 = 0; t16 < 16; t16++) {
        const int tok = wid * 16 + t16;
        const float v0 = Cs[tok * CPAD + lane];
        const float v1 = Cs[tok * CPAD + lane + 32];
        const long gtok = tokenBase + tok;

        float* crow = C + gtok * E_DIM;
        crow[lane] = v0;
        crow[lane + 32] = v1;

        float m = fmaxf(v0, v1);
#pragma unroll
        for (int o = 16; o; o >>= 1) m = fmaxf(m, __shfl_xor_sync(0xffffffffu, m, o));

        float e0 = __expf(v0 - m);
        float e1 = __expf(v1 - m);
        float s = e0 + e1;
#pragma unroll
        for (int o = 16; o; o >>= 1) s += __shfl_xor_sync(0xffffffffu, s, o);
        float inv = 1.0f / s;

        float* prow = P + gtok * E_DIM;
        prow[lane] = e0 * inv;
        prow[lane + 32] = e1 * inv;

        float bv; int bi;
        if (v0 >= v1) { bv = v0; bi = lane; } else { bv = v1; bi = lane + 32; }
#pragma unroll
        for (int o = 16; o; o >>= 1) {
            float ov = __shfl_xor_sync(0xffffffffu, bv, o);
            int   oi = __shfl_xor_sync(0xffffffffu, bi, o);
            if (ov > bv || (ov == bv && oi < bi)) { bv = ov; bi = oi; }
        }
        float c0 = (lane == bi) ? -INFINITY : v0;
        float c1 = (lane + 32 == bi) ? -INFINITY : v1;
        float sv; int si;
        if (c0 >= c1) { sv = c0; si = lane; } else { sv = c1; si = lane + 32; }
#pragma unroll
        for (int o = 16; o; o >>= 1) {
            float ov = __shfl_xor_sync(0xffffffffu, sv, o);
            int   oi = __shfl_xor_sync(0xffffffffu, si, o);
            if (ov > sv || (ov == sv && oi < si)) { sv = ov; si = oi; }
        }
        float d0 = (lane == bi || lane == si) ? -INFINITY : v0;
        float d1 = (lane + 32 == bi || lane + 32 == si) ? -INFINITY : v1;
        float tv = fmaxf(d0, d1);
#pragma unroll
        for (int o = 16; o; o >>= 1) tv = fmaxf(tv, __shfl_xor_sync(0xffffffffu, tv, o));

        if (lane == 0) {
            IDX[gtok * 2 + 0] = (float)bi;
            IDX[gtok * 2 + 1] = (float)si;
            if ((bv - sv) < GAP_THRESH || (sv - tv) < GAP_THRESH) {
                int slot = atomicAdd(&g_flag_count, 1);
                if (slot < 32768) g_flag_tokens[slot] = (int)gtok;
            }
        }
    }
}

// ---------------------------------------------------------------------------
// Exact fp64 recomputation for flagged near-tie tokens.
// ---------------------------------------------------------------------------
__global__ __launch_bounds__(64) void refine_ties(const float* __restrict__ A,
                                                  const float* __restrict__ W,
                                                  float* __restrict__ IDX) {
    __shared__ float sA[H_DIM];
    __shared__ double dred[2];
    __shared__ double dred2[2];
    __shared__ float af_s[E_DIM];

    int n = g_flag_count;
    if (n > 32768) n = 32768;

    const int e = threadIdx.x;
    const int lane = e & 31;
    const int wrp = e >> 5;

    for (int it = blockIdx.x; it < n; it += gridDim.x) {
        const int tok = g_flag_tokens[it];
        const float* arow = A + (long)tok * H_DIM;
        for (int k = threadIdx.x * 4; k < H_DIM; k += 64 * 4)
            *(float4*)(sA + k) = *(const float4*)(arow + k);
        __syncthreads();

        const float* wrow = W + (long)e * H_DIM;
        double a0 = 0, a1 = 0, a2 = 0, a3 = 0, a4 = 0, a5 = 0, a6 = 0, a7 = 0;
#pragma unroll 4
        for (int k = 0; k < H_DIM; k += 8) {
            float4 w0 = *(const float4*)(wrow + k);
            float4 w1 = *(const float4*)(wrow + k + 4);
            a0 = fma((double)sA[k + 0], (double)w0.x, a0);
            a1 = fma((double)sA[k + 1], (double)w0.y, a1);
            a2 = fma((double)sA[k + 2], (double)w0.z, a2);
            a3 = fma((double)sA[k + 3], (double)w0.w, a3);
            a4 = fma((double)sA[k + 4], (double)w1.x, a4);
            a5 = fma((double)sA[k + 5], (double)w1.y, a5);
            a6 = fma((double)sA[k + 6], (double)w1.z, a6);
            a7 = fma((double)sA[k + 7], (double)w1.w, a7);
        }
        double l = ((a0 + a1) + (a2 + a3)) + ((a4 + a5) + (a6 + a7));

        double mv = l;
#pragma unroll
        for (int o = 16; o; o >>= 1) {
            double ov = __shfl_xor_sync(0xffffffffu, mv, o);
            mv = ov > mv ? ov : mv;
        }
        if (lane == 0) dred[wrp] = mv;
        __syncthreads();
        const double m = dred[0] > dred[1] ? dred[0] : dred[1];

        const double ex = exp(l - m);
        double sm = ex;
#pragma unroll
        for (int o = 16; o; o >>= 1) sm += __shfl_xor_sync(0xffffffffu, sm, o);
        if (lane == 0) dred2[wrp] = sm;
        __syncthreads();
        const double s = dred2[0] + dred2[1];

        af_s[e] = (float)(ex / s);
        __syncthreads();

        if (e == 0) {
            int bi = 0;
#pragma unroll
            for (int i = 1; i < E_DIM; i++)
                if (af_s[i] > af_s[bi]) bi = i;
            int si = (bi == 0) ? 1 : 0;
#pragma unroll
            for (int i = 0; i < E_DIM; i++) {
                if (i == bi || i == si) continue;
                if (af_s[i] > af_s[si]) si = i;
            }
            IDX[(long)tok * 2 + 0] = (float)bi;
            IDX[(long)tok * 2 + 1] = (float)si;
        }
        __syncthreads();
    }
}

// ---------------------------------------------------------------------------
// d_out: [logits T*64 | affinities T*64 | indices-as-float T*2], fp32.
// ---------------------------------------------------------------------------
extern "C" void kernel_launch(void* const* d_in, const int* in_sizes, int n_in,
                              void* d_out, int out_size) {
    const float* A = (const float*)d_in[0];
    const float* W = (const float*)d_in[1];
    const int T = in_sizes[0] / H_DIM;  // 32768

    float* out = (float*)d_out;
    float* logits = out;
    float* affin  = out + (long)T * E_DIM;
    float* idx    = out + 2L * T * E_DIM;

    w_half<<<256, 256>>>(W);
    router_gemm_mma<<<T / TILE_M, 256>>>(A, logits, affin, idx);
    refine_ties<<<128, 64>>>(A, W, idx);
}

// round 10
// speedup vs baseline: 8.0359x; 7.6746x over previous
#include <cuda_runtime.h>
#include <cuda_bf16.h>
#include <cstdint>
#include <math.h>

#define H_DIM 4096
#define E_DIM 64
#define TILE_M 128
#define KCHUNK 32
#define NCHUNKS (H_DIM / KCHUNK)   // 128
#define GAP_THRESH 5e-4f
#define CPAD 68

// stage layout (bytes), SW64-swizzled tight tiles (64 B rows)
#define OFF_AHI 0
#define OFF_ALO 8192
#define OFF_BHI 16384
#define OFF_BLO 20480
#define STAGE_BYTES 24576
#define SMEM_BYTES 49152          // 2 stages; epilogue C-stage overlays

// byte offset of (row, 16B-chunk c) in a SW64-swizzled 64B-row tile
#define SWZ(r, c) ((uint32_t)((r) * 64 + ((((c) ^ (((r) >> 1) & 3))) << 4)))

__device__ __forceinline__ uint32_t smem_to_u32(const void* p) {
    uint32_t a;
    asm("{ .reg .u64 t; cvta.to.shared.u64 t, %1; cvt.u32.u64 %0, t; }" : "=r"(a) : "l"(p));
    return a;
}

#define LDSM_X4(r0, r1, r2, r3, addr)                                          \
    asm volatile("ldmatrix.sync.aligned.m8n8.x4.shared.b16 {%0,%1,%2,%3}, [%4];" \
                 : "=r"(r0), "=r"(r1), "=r"(r2), "=r"(r3) : "r"(addr))

__device__ __forceinline__ void mma_bf16(float* c, const uint32_t* a,
                                         uint32_t b0, uint32_t b1) {
    asm volatile(
        "mma.sync.aligned.m16n8k16.row.col.f32.bf16.bf16.f32 "
        "{%0,%1,%2,%3}, {%4,%5,%6,%7}, {%8,%9}, {%0,%1,%2,%3};"
        : "+f"(c[0]), "+f"(c[1]), "+f"(c[2]), "+f"(c[3])
        : "r"(a[0]), "r"(a[1]), "r"(a[2]), "r"(a[3]), "r"(b0), "r"(b1));
}

__device__ __forceinline__ uint32_t bf2(float a, float b) {
    __nv_bfloat162 t = __floats2bfloat162_rn(a, b);
    return *(uint32_t*)&t;
}

// split 8 fp32 -> 16B bf16 hi + 16B bf16 lo
__device__ __forceinline__ void split8(const float4 p0, const float4 p1,
                                       uint4& hi, uint4& lo) {
    hi.x = bf2(p0.x, p0.y); hi.y = bf2(p0.z, p0.w);
    hi.z = bf2(p1.x, p1.y); hi.w = bf2(p1.z, p1.w);
    float hx = __uint_as_float(hi.x << 16), hy = __uint_as_float(hi.x & 0xffff0000u);
    float hz = __uint_as_float(hi.y << 16), hw = __uint_as_float(hi.y & 0xffff0000u);
    lo.x = bf2(p0.x - hx, p0.y - hy); lo.y = bf2(p0.z - hz, p0.w - hw);
    hx = __uint_as_float(hi.z << 16); hy = __uint_as_float(hi.z & 0xffff0000u);
    hz = __uint_as_float(hi.w << 16); hw = __uint_as_float(hi.w & 0xffff0000u);
    lo.z = bf2(p1.x - hx, p1.y - hy); lo.w = bf2(p1.z - hz, p1.w - hw);
}

// ---------------------------------------------------------------------------
// Globals: pre-split W (bf16 hi/lo) + near-tie flag list
// ---------------------------------------------------------------------------
__device__ __nv_bfloat16 g_Whi[E_DIM * H_DIM];
__device__ __nv_bfloat16 g_Wlo[E_DIM * H_DIM];
__device__ int g_flag_count;
__device__ int g_flag_tokens[32768];

__global__ __launch_bounds__(256) void w_split(const float* __restrict__ W) {
    if (blockIdx.x == 0 && threadIdx.x == 0) g_flag_count = 0;
    for (int i = blockIdx.x * 256 + threadIdx.x; i < E_DIM * H_DIM; i += 256 * 256) {
        float w = W[i];
        __nv_bfloat16 hi = __float2bfloat16_rn(w);
        g_Whi[i] = hi;
        g_Wlo[i] = __float2bfloat16_rn(w - __bfloat162float(hi));
    }
}

// ---------------------------------------------------------------------------
// HMMA GEMM (bf16 hi/lo, 3 passes), double-buffered + fused epilogue.
// (identical to the validated 641us round-7 kernel)
// ---------------------------------------------------------------------------
__global__ __launch_bounds__(256, 2) void router_gemm_mma(const float* __restrict__ A,
                                                          float* __restrict__ C,
                                                          float* __restrict__ P,
                                                          float* __restrict__ IDX) {
    __shared__ __align__(16) char smem[SMEM_BYTES];
    const uint32_t sb = smem_to_u32(smem);
    float* Cs = (float*)smem;

    const int tid = threadIdx.x;
    const int wid = tid >> 5;
    const int lane = tid & 31;
    const long tokenBase = (long)blockIdx.x * TILE_M;

    float acc[8][4];
#pragma unroll
    for (int j = 0; j < 8; j++)
#pragma unroll
        for (int i = 0; i < 4; i++) acc[j][i] = 0.0f;

    const int lrow = tid >> 2;           // 0..63
    const int lc = tid & 3;              // chunk
    const int lel = lc * 8;              // elem offset
    const float* aP0 = A + (tokenBase + lrow) * H_DIM + lel;
    const float* aP1 = A + (tokenBase + lrow + 64) * H_DIM + lel;
    const __nv_bfloat16* whP = g_Whi + (long)lrow * H_DIM + lel;
    const __nv_bfloat16* wlP = g_Wlo + (long)lrow * H_DIM + lel;
    const uint32_t sA0 = SWZ(lrow, lc), sA1 = SWZ(lrow + 64, lc), sB = SWZ(lrow, lc);

    const int arow = wid * 16 + (lane & 15);
    const uint32_t axr = (uint32_t)((arow >> 1) & 3);
    const uint32_t ahalf = (uint32_t)((lane >> 4) & 1);
    const int ebase = (lane & 7) + ((lane >> 4) & 1) * 8;
    const uint32_t bxr = (uint32_t)((ebase >> 1) & 3);
    const uint32_t bhalf = (uint32_t)((lane >> 3) & 1);

    float4 p00 = *(const float4*)(aP0), p01 = *(const float4*)(aP0 + 4);
    float4 p10 = *(const float4*)(aP1), p11 = *(const float4*)(aP1 + 4);
    uint4 wh = *(const uint4*)(whP), wl = *(const uint4*)(wlP);
    {
        uint4 h0, l0, h1, l1;
        split8(p00, p01, h0, l0);
        split8(p10, p11, h1, l1);
        *(uint4*)(smem + OFF_AHI + sA0) = h0;
        *(uint4*)(smem + OFF_ALO + sA0) = l0;
        *(uint4*)(smem + OFF_AHI + sA1) = h1;
        *(uint4*)(smem + OFF_ALO + sA1) = l1;
        *(uint4*)(smem + OFF_BHI + sB) = wh;
        *(uint4*)(smem + OFF_BLO + sB) = wl;
    }
    __syncthreads();

    for (int chunk = 0; chunk < NCHUNKS; chunk++) {
        const uint32_t cb = (uint32_t)((chunk & 1) * STAGE_BYTES);
        const uint32_t nb = (uint32_t)(((chunk + 1) & 1) * STAGE_BYTES);
        const bool more = (chunk + 1 < NCHUNKS);

        if (more) {
            const int kb = (chunk + 1) * KCHUNK;
            p00 = *(const float4*)(aP0 + kb); p01 = *(const float4*)(aP0 + kb + 4);
            p10 = *(const float4*)(aP1 + kb); p11 = *(const float4*)(aP1 + kb + 4);
            wh = *(const uint4*)(whP + kb);   wl = *(const uint4*)(wlP + kb);
        }

#pragma unroll
        for (int s = 0; s < 2; s++) {
            uint32_t ah[4], al[4];
            {
                const uint32_t ach = (uint32_t)(2 * s) + ahalf;
                const uint32_t ao = (uint32_t)(arow * 64) + ((ach ^ axr) << 4);
                LDSM_X4(ah[0], ah[1], ah[2], ah[3], sb + cb + OFF_AHI + ao);
                LDSM_X4(al[0], al[1], al[2], al[3], sb + cb + OFF_ALO + ao);
            }
            uint32_t bh[16], bl[16];
#pragma unroll
            for (int jt = 0; jt < 4; jt++) {
                const int erow = jt * 16 + ebase;
                const uint32_t bch = (uint32_t)(2 * s) + bhalf;
                const uint32_t bo = (uint32_t)(erow * 64) + ((bch ^ bxr) << 4);
                LDSM_X4(bh[4 * jt], bh[4 * jt + 1], bh[4 * jt + 2], bh[4 * jt + 3],
                        sb + cb + OFF_BHI + bo);
                LDSM_X4(bl[4 * jt], bl[4 * jt + 1], bl[4 * jt + 2], bl[4 * jt + 3],
                        sb + cb + OFF_BLO + bo);
            }
#pragma unroll
            for (int jt = 0; jt < 4; jt++) {
                mma_bf16(acc[2 * jt], ah, bh[4 * jt], bh[4 * jt + 1]);
                mma_bf16(acc[2 * jt + 1], ah, bh[4 * jt + 2], bh[4 * jt + 3]);
            }
#pragma unroll
            for (int jt = 0; jt < 4; jt++) {
                mma_bf16(acc[2 * jt], ah, bl[4 * jt], bl[4 * jt + 1]);
                mma_bf16(acc[2 * jt + 1], ah, bl[4 * jt + 2], bl[4 * jt + 3]);
            }
#pragma unroll
            for (int jt = 0; jt < 4; jt++) {
                mma_bf16(acc[2 * jt], al, bh[4 * jt], bh[4 * jt + 1]);
                mma_bf16(acc[2 * jt + 1], al, bh[4 * jt + 2], bh[4 * jt + 3]);
            }
        }

        if (more) {
            uint4 h0, l0, h1, l1;
            split8(p00, p01, h0, l0);
            split8(p10, p11, h1, l1);
            *(uint4*)(smem + nb + OFF_AHI + sA0) = h0;
            *(uint4*)(smem + nb + OFF_ALO + sA0) = l0;
            *(uint4*)(smem + nb + OFF_AHI + sA1) = h1;
            *(uint4*)(smem + nb + OFF_ALO + sA1) = l1;
            *(uint4*)(smem + nb + OFF_BHI + sB) = wh;
            *(uint4*)(smem + nb + OFF_BLO + sB) = wl;
        }
        __syncthreads();
    }

    {
        const int r0 = wid * 16 + (lane >> 2);
        const int cbo = 2 * (lane & 3);
#pragma unroll
        for (int j = 0; j < 8; j++) {
            const int col = j * 8 + cbo;
            *(float2*)(Cs + r0 * CPAD + col) = make_float2(acc[j][0], acc[j][1]);
            *(float2*)(Cs + (r0 + 8) * CPAD + col) = make_float2(acc[j][2], acc[j][3]);
        }
    }
    __syncthreads();

#pragma unroll 1
    for (int t16 = 0; t16 < 16; t16++) {
        const int tok = wid * 16 + t16;
        const float v0 = Cs[tok * CPAD + lane];
        const float v1 = Cs[tok * CPAD + lane + 32];
        const long gtok = tokenBase + tok;

        float* crow = C + gtok * E_DIM;
        crow[lane] = v0;
        crow[lane + 32] = v1;

        float m = fmaxf(v0, v1);
#pragma unroll
        for (int o = 16; o; o >>= 1) m = fmaxf(m, __shfl_xor_sync(0xffffffffu, m, o));

        float e0 = __expf(v0 - m);
        float e1 = __expf(v1 - m);
        float s = e0 + e1;
#pragma unroll
        for (int o = 16; o; o >>= 1) s += __shfl_xor_sync(0xffffffffu, s, o);
        float inv = 1.0f / s;

        float* prow = P + gtok * E_DIM;
        prow[lane] = e0 * inv;
        prow[lane + 32] = e1 * inv;

        float bv; int bi;
        if (v0 >= v1) { bv = v0; bi = lane; } else { bv = v1; bi = lane + 32; }
#pragma unroll
        for (int o = 16; o; o >>= 1) {
            float ov = __shfl_xor_sync(0xffffffffu, bv, o);
            int   oi = __shfl_xor_sync(0xffffffffu, bi, o);
            if (ov > bv || (ov == bv && oi < bi)) { bv = ov; bi = oi; }
        }
        float c0 = (lane == bi) ? -INFINITY : v0;
        float c1 = (lane + 32 == bi) ? -INFINITY : v1;
        float sv; int si;
        if (c0 >= c1) { sv = c0; si = lane; } else { sv = c1; si = lane + 32; }
#pragma unroll
        for (int o = 16; o; o >>= 1) {
            float ov = __shfl_xor_sync(0xffffffffu, sv, o);
            int   oi = __shfl_xor_sync(0xffffffffu, si, o);
            if (ov > sv || (ov == sv && oi < si)) { sv = ov; si = oi; }
        }
        float d0 = (lane == bi || lane == si) ? -INFINITY : v0;
        float d1 = (lane + 32 == bi || lane + 32 == si) ? -INFINITY : v1;
        float tv = fmaxf(d0, d1);
#pragma unroll
        for (int o = 16; o; o >>= 1) tv = fmaxf(tv, __shfl_xor_sync(0xffffffffu, tv, o));

        if (lane == 0) {
            IDX[gtok * 2 + 0] = (float)bi;
            IDX[gtok * 2 + 1] = (float)si;
            if ((bv - sv) < GAP_THRESH || (sv - tv) < GAP_THRESH) {
                int slot = atomicAdd(&g_flag_count, 1);
                if (slot < 32768) g_flag_tokens[slot] = (int)gtok;
            }
        }
    }
}

// ---------------------------------------------------------------------------
// Refine v3: fp64-FREE compensated-fp32 recomputation for near-tie tokens.
// 256 threads: 4 threads per expert, 1024 k-elems each. Dot product uses
// TwoSum + exact-FMA product error (error ~1e-9 << reference's own 2e-7).
// fp64 used only for 64 parallel exps + small reductions (latency-hidden).
// ---------------------------------------------------------------------------
__global__ __launch_bounds__(256) void refine_ties(const float* __restrict__ A,
                                                   const float* __restrict__ W,
                                                   float* __restrict__ IDX) {
    __shared__ float sA[H_DIM];
    __shared__ double dpart[E_DIM][4];
    __shared__ double dsum[2];
    __shared__ float fmx[2];
    __shared__ float af_s[E_DIM];

    int n = g_flag_count;
    if (n > 32768) n = 32768;

    const int t = threadIdx.x;
    const int e = t & 63;
    const int seg = t >> 6;      // 0..3

    for (int it = blockIdx.x; it < n; it += gridDim.x) {
        const int tok = g_flag_tokens[it];
        const float* arow = A + (long)tok * H_DIM;
        for (int k = t * 4; k < H_DIM; k += 1024)
            *(float4*)(sA + k) = *(const float4*)(arow + k);
        __syncthreads();

        // compensated fp32 dot over this thread's 1024-element segment
        const float* wrow = W + (long)e * H_DIM + seg * 1024;
        const float* aseg = sA + seg * 1024;
        float s = 0.0f, c = 0.0f, ce = 0.0f;
#pragma unroll 4
        for (int k = 0; k < 1024; k += 4) {
            float4 w4 = *(const float4*)(wrow + k);
            float4 a4 = *(const float4*)(aseg + k);
#define ACC1(av, wv) {                                   \
            float p = __fmul_rn((av), (wv));             \
            ce += __fmaf_rn((av), (wv), -p);             \
            float t2 = __fadd_rn(s, p);                  \
            float z = t2 - s;                            \
            c += (s - (t2 - z)) + (p - z);               \
            s = t2; }
            ACC1(a4.x, w4.x); ACC1(a4.y, w4.y);
            ACC1(a4.z, w4.z); ACC1(a4.w, w4.w);
#undef ACC1
        }
        dpart[e][seg] = (double)s + ((double)c + (double)ce);
        __syncthreads();

        // threads 0..63: combine segments, softmax, top-2
        double dl = 0.0, ex = 0.0;
        float fl = 0.0f;
        if (t < 64) {
            dl = (dpart[e][0] + dpart[e][1]) + (dpart[e][2] + dpart[e][3]);
            fl = (float)dl;
            // max over 64 (approximate max in fp32 is fine for stability)
            float mv = fl;
#pragma unroll
            for (int o = 16; o; o >>= 1)
                mv = fmaxf(mv, __shfl_xor_sync(0xffffffffu, mv, o));
            if ((t & 31) == 0) fmx[t >> 5] = mv;
        }
        __syncthreads();
        if (t < 64) {
            const float m = fmaxf(fmx[0], fmx[1]);
            ex = exp(dl - (double)m);   // fp64 exp, 64 in parallel
            double sm = ex;
#pragma unroll
            for (int o = 16; o; o >>= 1)
                sm += __shfl_xor_sync(0xffffffffu, sm, o);
            if ((t & 31) == 0) dsum[t >> 5] = sm;
        }
        __syncthreads();
        if (t < 64) {
            const double stot = dsum[0] + dsum[1];
            af_s[e] = (float)(ex / stot);
        }
        __syncthreads();

        if (t == 0) {
            int bi = 0;
#pragma unroll
            for (int i = 1; i < E_DIM; i++)
                if (af_s[i] > af_s[bi]) bi = i;   // ties keep lower index
            int si = (bi == 0) ? 1 : 0;
#pragma unroll
            for (int i = 0; i < E_DIM; i++) {
                if (i == bi || i == si) continue;
                if (af_s[i] > af_s[si]) si = i;
            }
            IDX[(long)tok * 2 + 0] = (float)bi;
            IDX[(long)tok * 2 + 1] = (float)si;
        }
        __syncthreads();
    }
}

// ---------------------------------------------------------------------------
// d_out: [logits T*64 | affinities T*64 | indices-as-float T*2], fp32.
// ---------------------------------------------------------------------------
extern "C" void kernel_launch(void* const* d_in, const int* in_sizes, int n_in,
                              void* d_out, int out_size) {
    const float* A = (const float*)d_in[0];
    const float* W = (const float*)d_in[1];
    const int T = in_sizes[0] / H_DIM;  // 32768

    float* out = (float*)d_out;
    float* logits = out;
    float* affin  = out + (long)T * E_DIM;
    float* idx    = out + 2L * T * E_DIM;

    w_split<<<256, 256>>>(W);
    router_gemm_mma<<<T / TILE_M, 256>>>(A, logits, affin, idx);
    refine_ties<<<256, 256>>>(A, W, idx);
}